// round 5
// baseline (speedup 1.0000x reference)
#include <cuda_runtime.h>
#include <cuda_bf16.h>
#include <math.h>
#include <stdint.h>

#define NN 50000
#define EE 800000
#define DD 200
#define NPAD 208          // padded row count for weights (N dim)
#define KC 640            // concat K: [0,208) hi | [208,416) mid | [416,624) lo-part | pad
#define BM 128            // M tile
#define KT 64             // K chunk
#define AST 72            // smem row stride (bf16 elems) -> 144B, conflict-free ldmatrix
#define NTILES ((NN + BM - 1) / BM)   // 391

// ================= device scratch =================
__device__ __align__(128) float g_agg[NN * DD];
__device__ __align__(128) float g_h1[NN * DD];
__device__ __align__(128) float g_norm[NN];
__device__ __align__(128) float g_lw2t[DD * DD];
__device__ __align__(128) float g_bfin[DD];
// K-concat bf16 operands. A-side: [hi | hi | lo]. B-side: [hi | lo | hi].
__device__ __align__(128) __nv_bfloat16 g_xcat[NN * KC];
__device__ __align__(128) __nv_bfloat16 g_h1cat[NN * KC];
__device__ __align__(128) __nv_bfloat16 g_a2cat[NN * KC];
__device__ __align__(128) __nv_bfloat16 g_h0cat[NN * KC];
__device__ __align__(128) __nv_bfloat16 g_w1cat[NPAD * KC];
__device__ __align__(128) __nv_bfloat16 g_wihcat[NPAD * KC];
__device__ __align__(128) __nv_bfloat16 g_whhcat[NPAD * KC];
__device__ __align__(128) __nv_bfloat16 g_mtcat[NPAD * KC];

// ================= degree / norm =================
__global__ void deg_kernel(const int* __restrict__ dst) {
    int e = blockIdx.x * blockDim.x + threadIdx.x;
    if (e < EE) atomicAdd(&g_norm[dst[e]], 1.0f);
}
__global__ void norm_kernel() {
    int n = blockIdx.x * blockDim.x + threadIdx.x;
    if (n < NN) {
        float d = g_norm[n];
        g_norm[n] = (d > 0.0f) ? (1.0f / d) : 0.0f;
    }
}

// ================= edge message + scatter (R1-proven) =================
__global__ void edge_kernel(const float* __restrict__ x,
                            const int* __restrict__ src,
                            const int* __restrict__ dst,
                            const int* __restrict__ et,
                            const float* __restrict__ w) {
    int idx = blockIdx.x * blockDim.x + threadIdx.x;
    if (idx >= EE * 50) return;
    int e  = idx / 50;
    int b2 = idx - e * 50;

    int s = __ldg(&src[e]);
    int d = __ldg(&dst[e]);
    int r = __ldg(&et[e]);

    float4 xv = *(const float4*)(x + (long)s * DD + b2 * 4);
    const float4* wp = (const float4*)(w + (long)r * 400 + b2 * 8);
    float4 wA = wp[0];
    float4 wB = wp[1];

    float o0 = xv.x * wA.x + xv.y * wA.z;
    float o1 = xv.x * wA.y + xv.y * wA.w;
    float o2 = xv.z * wB.x + xv.w * wB.z;
    float o3 = xv.z * wB.y + xv.w * wB.w;

    float* ap = g_agg + (long)d * DD + b2 * 4;
    asm volatile("red.global.add.v4.f32 [%0], {%1, %2, %3, %4};"
                 :: "l"(ap), "f"(o0), "f"(o1), "f"(o2), "f"(o3) : "memory");
}

// ================= conversions into K-concat layout =================
// A-side node arrays: seg0=hi, seg1=hi, seg2=lo, pads zero.
__global__ void conv_node(const float* __restrict__ src,
                          __nv_bfloat16* __restrict__ dstc, int useNorm) {
    long idx = (long)blockIdx.x * blockDim.x + threadIdx.x;
    if (idx >= (long)NN * KC) return;
    int n = (int)(idx / KC);
    int c = (int)(idx - (long)n * KC);
    int seg = c / NPAD;          // 0,1,2 (3 only for pad 624..639)
    int cc = c - seg * NPAD;
    __nv_bfloat16 outv = __float2bfloat16(0.0f);
    if (seg < 3 && cc < DD) {
        float v = src[(long)n * DD + cc];
        if (useNorm) v *= g_norm[n];
        __nv_bfloat16 h = __float2bfloat16(v);
        if (seg < 2) outv = h;
        else outv = __float2bfloat16(v - __bfloat162float(h));
    }
    dstc[idx] = outv;
}

// B-side weights: seg0=hi, seg1=lo, seg2=hi; transpose flag: B[j][k]=src[k][j].
__global__ void conv_weight(const float* __restrict__ src,
                            __nv_bfloat16* __restrict__ dstc, int transpose) {
    int idx = blockIdx.x * blockDim.x + threadIdx.x;
    if (idx >= NPAD * KC) return;
    int j = idx / KC;
    int c = idx - j * KC;
    int seg = c / NPAD;
    int cc = c - seg * NPAD;
    __nv_bfloat16 outv = __float2bfloat16(0.0f);
    if (j < DD && seg < 3 && cc < DD) {
        float v = transpose ? src[cc * DD + j] : src[j * DD + cc];
        __nv_bfloat16 h = __float2bfloat16(v);
        if (seg != 1) outv = h;
        else outv = __float2bfloat16(v - __bfloat162float(h));
    }
    dstc[idx] = outv;
}

__global__ void tr_lw2(const float* __restrict__ lw2) {
    int idx = blockIdx.x * blockDim.x + threadIdx.x;
    if (idx >= DD * DD) return;
    int t = idx / DD, u = idx - t * DD;
    g_lw2t[u * DD + t] = lw2[idx];
}

// M[j][t] = sum_u Wih[j][u] * lw2[t][u]  -> mtcat (B-side layout)
__global__ void bmt_kernel(const float* __restrict__ Wih) {
    __shared__ float row[DD];
    int j = blockIdx.x;       // 0..207
    if (j < DD)
        for (int i = threadIdx.x; i < DD; i += 256) row[i] = Wih[j * DD + i];
    __syncthreads();
    int t = threadIdx.x;
    if (t < NPAD) {
        float s = 0.0f;
        if (j < DD && t < DD) {
#pragma unroll 4
            for (int u = 0; u < DD; u++) s += row[u] * g_lw2t[u * DD + t];
        }
        __nv_bfloat16 h = __float2bfloat16(s);
        __nv_bfloat16 l = __float2bfloat16(s - __bfloat162float(h));
        g_mtcat[j * KC + t] = h;
        g_mtcat[j * KC + NPAD + t] = l;
        g_mtcat[j * KC + 2 * NPAD + t] = h;
    }
    // pad columns 624..639
    if (threadIdx.x < 16)
        g_mtcat[j * KC + 624 + threadIdx.x] = __float2bfloat16(0.0f);
}

// bfin[j] = bih[j] + bhh[j] + sum_t b2[t]*Wih[j][t]
__global__ void bias_kernel(const float* __restrict__ b2, const float* __restrict__ Wih,
                            const float* __restrict__ bih, const float* __restrict__ bhh) {
    __shared__ float b2s[DD];
    for (int i = threadIdx.x; i < DD; i += 256) b2s[i] = b2[i];
    __syncthreads();
    int j = threadIdx.x;
    if (j >= DD) return;
    float s = bih[j] + bhh[j];
#pragma unroll 4
    for (int t = 0; t < DD; t++) s += b2s[t] * Wih[j * DD + t];
    g_bfin[j] = s;
}

// ================= mma.sync GEMM =================
__device__ __forceinline__ uint32_t smem_u32(const void* p) {
    return (uint32_t)__cvta_generic_to_shared(p);
}
__device__ __forceinline__ void ldsm4(uint32_t* r, uint32_t addr) {
    asm volatile("ldmatrix.sync.aligned.m8n8.x4.shared.b16 {%0,%1,%2,%3}, [%4];"
                 : "=r"(r[0]), "=r"(r[1]), "=r"(r[2]), "=r"(r[3]) : "r"(addr));
}
__device__ __forceinline__ void ldsm2(uint32_t* r, uint32_t addr) {
    asm volatile("ldmatrix.sync.aligned.m8n8.x2.shared.b16 {%0,%1}, [%2];"
                 : "=r"(r[0]), "=r"(r[1]) : "r"(addr));
}
__device__ __forceinline__ void mma_bf16(float* c, const uint32_t* a, const uint32_t* b) {
    asm volatile(
        "mma.sync.aligned.m16n8k16.row.col.f32.bf16.bf16.f32 "
        "{%0,%1,%2,%3}, {%4,%5,%6,%7}, {%8,%9}, {%0,%1,%2,%3};"
        : "+f"(c[0]), "+f"(c[1]), "+f"(c[2]), "+f"(c[3])
        : "r"(a[0]), "r"(a[1]), "r"(a[2]), "r"(a[3]), "r"(b[0]), "r"(b[1]));
}

// C[128 x 200] per CTA: C = sum_p Acat_p @ Bcat_p^T  (K=640 concat does hi/lo comp)
// 8 warps: 4(M) x 2(N); warp tile 32 x 104 (2 m16 x 13 n8).
template <int NPASS, bool HAS_AGG, bool WRITE_H1>
__global__ void __launch_bounds__(256, 1) mma_gemm(
    const __nv_bfloat16* __restrict__ A0, const __nv_bfloat16* __restrict__ B0,
    const __nv_bfloat16* __restrict__ A1, const __nv_bfloat16* __restrict__ B1,
    const __nv_bfloat16* __restrict__ A2, const __nv_bfloat16* __restrict__ B2,
    const float* __restrict__ bias, float* __restrict__ outf,
    __nv_bfloat16* __restrict__ h1cat) {
    __shared__ __align__(16) __nv_bfloat16 As[BM * AST];     // 18432 B
    __shared__ __align__(16) __nv_bfloat16 Bs[NPAD * AST];   // 29952 B

    int tid = threadIdx.x;
    int lane = tid & 31;
    int wid = tid >> 5;
    int wm = wid & 3;          // 0..3 -> M offset wm*32
    int wn = wid >> 2;         // 0..1 -> N offset wn*104
    int row0 = blockIdx.x * BM;

    float acc[2][13][4];
#pragma unroll
    for (int mi = 0; mi < 2; mi++)
#pragma unroll
        for (int nt = 0; nt < 13; nt++)
#pragma unroll
            for (int q = 0; q < 4; q++) acc[mi][nt][q] = 0.0f;

    // precomputed ldmatrix smem addresses (per-lane, chunk-invariant parts)
    int a_row = wm * 32 + (lane & 15);
    int a_col0 = (lane >> 4) << 3;
    int b_row_base = wn * 104 + (lane & 7) + ((lane >> 4) << 3);
    int b_col0 = ((lane >> 3) & 1) << 3;
    int b2_row = wn * 104 + 96 + (lane & 7);   // last n-tile (x2)
    int b2_col0 = ((lane >> 3) & 1) << 3;

#pragma unroll 1
    for (int p = 0; p < NPASS; p++) {
        const __nv_bfloat16* A = (p == 0) ? A0 : ((p == 1) ? A1 : A2);
        const __nv_bfloat16* B = (p == 0) ? B0 : ((p == 1) ? B1 : B2);
#pragma unroll 1
        for (int kb = 0; kb < KC; kb += KT) {
            __syncthreads();
            // A chunk: 128 rows x 64 cols = 1024 uint4
            for (int i = tid; i < 1024; i += 256) {
                int r = i >> 3, u = i & 7;
                int gr = row0 + r;
                uint4 v = make_uint4(0, 0, 0, 0);
                if (gr < NN) v = *((const uint4*)(A + (long)gr * KC + kb) + u);
                *((uint4*)(As + r * AST) + u) = v;
            }
            // B chunk: 208 rows x 64 cols = 1664 uint4
            for (int i = tid; i < 1664; i += 256) {
                int r = i >> 3, u = i & 7;
                *((uint4*)(Bs + r * AST) + u) = *((const uint4*)(B + (long)r * KC + kb) + u);
            }
            __syncthreads();
#pragma unroll
            for (int k16 = 0; k16 < 4; k16++) {
                int kk = k16 << 4;
                uint32_t afr[2][4];
#pragma unroll
                for (int mi = 0; mi < 2; mi++) {
                    uint32_t addr = smem_u32(As + (a_row + mi * 16) * AST + kk + a_col0);
                    ldsm4(afr[mi], addr);
                }
#pragma unroll
                for (int bt = 0; bt < 6; bt++) {
                    uint32_t bfr[4];
                    uint32_t addr = smem_u32(Bs + (b_row_base + bt * 16) * AST + kk + b_col0);
                    ldsm4(bfr, addr);
                    mma_bf16(acc[0][2 * bt],     afr[0], bfr);
                    mma_bf16(acc[0][2 * bt + 1], afr[0], bfr + 2);
                    mma_bf16(acc[1][2 * bt],     afr[1], bfr);
                    mma_bf16(acc[1][2 * bt + 1], afr[1], bfr + 2);
                }
                {
                    uint32_t bfr[2];
                    uint32_t addr = smem_u32(Bs + b2_row * AST + kk + b2_col0);
                    ldsm2(bfr, addr);
                    mma_bf16(acc[0][12], afr[0], bfr);
                    mma_bf16(acc[1][12], afr[1], bfr);
                }
            }
        }
    }

    // ---- epilogue ----
#pragma unroll
    for (int mi = 0; mi < 2; mi++) {
        int r0 = row0 + wm * 32 + mi * 16 + (lane >> 2);   // rows r0 and r0+8
#pragma unroll
        for (int half = 0; half < 2; half++) {
            int gr = r0 + half * 8;
            if (gr >= NN) continue;
            float nv = HAS_AGG ? g_norm[gr] : 0.0f;
#pragma unroll
            for (int nt = 0; nt < 13; nt++) {
                int col = wn * 104 + nt * 8 + ((lane & 3) << 1);
                if (col >= DD) continue;
                float v0 = acc[mi][nt][half * 2 + 0];
                float v1 = acc[mi][nt][half * 2 + 1];
                if (HAS_AGG) {
                    float2 ag = *(const float2*)(g_agg + (long)gr * DD + col);
                    v0 += ag.x * nv;
                    v1 += ag.y * nv;
                }
                float2 bb = *(const float2*)(bias + col);
                v0 = tanhf(v0 + bb.x);
                v1 = tanhf(v1 + bb.y);
                *(float2*)(outf + (long)gr * DD + col) = make_float2(v0, v1);
                if (WRITE_H1) {
                    __nv_bfloat16 h0b = __float2bfloat16(v0);
                    __nv_bfloat16 h1b = __float2bfloat16(v1);
                    __nv_bfloat162 hp; hp.x = h0b; hp.y = h1b;
                    __nv_bfloat162 lp;
                    lp.x = __float2bfloat16(v0 - __bfloat162float(h0b));
                    lp.y = __float2bfloat16(v1 - __bfloat162float(h1b));
                    __nv_bfloat16* base = h1cat + (long)gr * KC + col;
                    *(__nv_bfloat162*)(base) = hp;
                    *(__nv_bfloat162*)(base + NPAD) = hp;
                    *(__nv_bfloat162*)(base + 2 * NPAD) = lp;
                }
            }
        }
    }
}

// ================= launch =================
extern "C" void kernel_launch(void* const* d_in, const int* in_sizes, int n_in,
                              void* d_out, int out_size) {
    const float* node_feat = (const float*)d_in[0];
    const float* dyn       = (const float*)d_in[1];
    const int*   src       = (const int*)d_in[2];
    const int*   dst       = (const int*)d_in[3];
    const int*   et        = (const int*)d_in[4];
    const float* w1        = (const float*)d_in[5];
    const float* lw1       = (const float*)d_in[6];
    const float* b1        = (const float*)d_in[7];
    const float* w2        = (const float*)d_in[8];
    const float* lw2       = (const float*)d_in[9];
    const float* b2        = (const float*)d_in[10];
    const float* Wih       = (const float*)d_in[11];
    const float* Whh       = (const float*)d_in[12];
    const float* bih       = (const float*)d_in[13];
    const float* bhh       = (const float*)d_in[14];
    float* out = (float*)d_out;

    void *agg_p, *norm_p, *h1_p, *bfin_p;
    void *xcat, *h1cat, *a2cat, *h0cat, *w1cat, *wihcat, *whhcat, *mtcat;
    cudaGetSymbolAddress(&agg_p, g_agg);
    cudaGetSymbolAddress(&norm_p, g_norm);
    cudaGetSymbolAddress(&h1_p, g_h1);
    cudaGetSymbolAddress(&bfin_p, g_bfin);
    cudaGetSymbolAddress(&xcat, g_xcat);
    cudaGetSymbolAddress(&h1cat, g_h1cat);
    cudaGetSymbolAddress(&a2cat, g_a2cat);
    cudaGetSymbolAddress(&h0cat, g_h0cat);
    cudaGetSymbolAddress(&w1cat, g_w1cat);
    cudaGetSymbolAddress(&wihcat, g_wihcat);
    cudaGetSymbolAddress(&whhcat, g_whhcat);
    cudaGetSymbolAddress(&mtcat, g_mtcat);

    cudaMemsetAsync(agg_p, 0, sizeof(float) * NN * DD);
    cudaMemsetAsync(norm_p, 0, sizeof(float) * NN);
    cudaMemsetAsync(h1cat, 0, sizeof(__nv_bfloat16) * (size_t)NN * KC);  // pads

    deg_kernel<<<(EE + 255) / 256, 256>>>(dst);
    norm_kernel<<<(NN + 255) / 256, 256>>>();

    // weight / operand prep
    conv_weight<<<(NPAD * KC + 255) / 256, 256>>>(lw1, (__nv_bfloat16*)w1cat, 1);
    conv_weight<<<(NPAD * KC + 255) / 256, 256>>>(Wih, (__nv_bfloat16*)wihcat, 0);
    conv_weight<<<(NPAD * KC + 255) / 256, 256>>>(Whh, (__nv_bfloat16*)whhcat, 0);
    tr_lw2<<<(DD * DD + 255) / 256, 256>>>(lw2);
    bmt_kernel<<<NPAD, 256>>>(Wih);
    bias_kernel<<<1, 256>>>(b2, Wih, bih, bhh);

    const long nconv = (long)NN * KC;
    conv_node<<<(int)((nconv + 255) / 256), 256>>>(node_feat, (__nv_bfloat16*)xcat, 0);
    conv_node<<<(int)((nconv + 255) / 256), 256>>>(dyn, (__nv_bfloat16*)h0cat, 0);

    // layer 1: scatter + GEMM (h1 fp32 + h1cat bf16 out of epilogue)
    edge_kernel<<<(EE * 50 + 255) / 256, 256>>>(node_feat, src, dst, et, w1);
    mma_gemm<1, true, true><<<NTILES, 256>>>(
        (const __nv_bfloat16*)xcat, (const __nv_bfloat16*)w1cat,
        nullptr, nullptr, nullptr, nullptr,
        b1, (float*)h1_p, (__nv_bfloat16*)h1cat);

    // layer 2 scatter + convert agg2*norm
    cudaMemsetAsync(agg_p, 0, sizeof(float) * NN * DD);
    edge_kernel<<<(EE * 50 + 255) / 256, 256>>>((const float*)h1_p, src, dst, et, w2);
    conv_node<<<(int)((nconv + 255) / 256), 256>>>((const float*)agg_p, (__nv_bfloat16*)a2cat, 1);

    // fused final: out = tanh( agg2n@Wih^T + h1@(lw2@Wih^T) + h0@Whh^T + bfin )
    mma_gemm<3, false, false><<<NTILES, 256>>>(
        (const __nv_bfloat16*)a2cat, (const __nv_bfloat16*)wihcat,
        (const __nv_bfloat16*)h1cat, (const __nv_bfloat16*)mtcat,
        (const __nv_bfloat16*)h0cat, (const __nv_bfloat16*)whhcat,
        (const float*)bfin_p, out, nullptr);
}

// round 6
// speedup vs baseline: 1.9192x; 1.9192x over previous
#include <cuda_runtime.h>
#include <cuda_bf16.h>
#include <math.h>
#include <stdint.h>

#define NN 50000
#define EE 800000
#define DD 200
#define KP 208            // padded K / padded N for weights
#define BM 128            // M tile per CTA
#define AST 72            // smem row stride in bf16 (144 B)
#define NTILES ((NN + BM - 1) / BM)   // 391

// smem stage layout (bytes)
#define SO_AHI 0
#define SO_ALO 18432
#define SO_BHI 36864
#define SO_BLO 66816
#define STAGE_BYTES 96768
#define SM_TOT (2 * STAGE_BYTES)      // 193536

// ================= device scratch =================
__device__ __align__(128) float g_agg[NN * DD];
__device__ __align__(128) float g_h1[NN * DD];
__device__ __align__(128) float g_norm[NN];
__device__ __align__(128) float g_lw2t[DD * DD];
__device__ __align__(128) float g_bfin[DD];
__device__ __align__(128) __nv_bfloat16 g_xhi[NN * KP],  g_xlo[NN * KP];
__device__ __align__(128) __nv_bfloat16 g_h1hi[NN * KP], g_h1lo[NN * KP];
__device__ __align__(128) __nv_bfloat16 g_a2hi[NN * KP], g_a2lo[NN * KP];
__device__ __align__(128) __nv_bfloat16 g_h0hi[NN * KP], g_h0lo[NN * KP];
__device__ __align__(128) __nv_bfloat16 g_w1hi[KP * KP],  g_w1lo[KP * KP];
__device__ __align__(128) __nv_bfloat16 g_wihhi[KP * KP], g_wihlo[KP * KP];
__device__ __align__(128) __nv_bfloat16 g_whhhi[KP * KP], g_whhlo[KP * KP];
__device__ __align__(128) __nv_bfloat16 g_mthi[KP * KP],  g_mtlo[KP * KP];

// ================= degree / norm =================
__global__ void deg_kernel(const int* __restrict__ dst) {
    int e = blockIdx.x * blockDim.x + threadIdx.x;
    if (e < EE) atomicAdd(&g_norm[dst[e]], 1.0f);
}
__global__ void norm_kernel() {
    int n = blockIdx.x * blockDim.x + threadIdx.x;
    if (n < NN) {
        float d = g_norm[n];
        g_norm[n] = (d > 0.0f) ? (1.0f / d) : 0.0f;
    }
}

// ================= edge message + scatter (R1-proven) =================
__global__ void edge_kernel(const float* __restrict__ x,
                            const int* __restrict__ src,
                            const int* __restrict__ dst,
                            const int* __restrict__ et,
                            const float* __restrict__ w) {
    int idx = blockIdx.x * blockDim.x + threadIdx.x;
    if (idx >= EE * 50) return;
    int e  = idx / 50;
    int b2 = idx - e * 50;

    int s = __ldg(&src[e]);
    int d = __ldg(&dst[e]);
    int r = __ldg(&et[e]);

    float4 xv = *(const float4*)(x + (long)s * DD + b2 * 4);
    const float4* wp = (const float4*)(w + (long)r * 400 + b2 * 8);
    float4 wA = wp[0];
    float4 wB = wp[1];

    float o0 = xv.x * wA.x + xv.y * wA.z;
    float o1 = xv.x * wA.y + xv.y * wA.w;
    float o2 = xv.z * wB.x + xv.w * wB.z;
    float o3 = xv.z * wB.y + xv.w * wB.w;

    float* ap = g_agg + (long)d * DD + b2 * 4;
    asm volatile("red.global.add.v4.f32 [%0], {%1, %2, %3, %4};"
                 :: "l"(ap), "f"(o0), "f"(o1), "f"(o2), "f"(o3) : "memory");
}

// ================= hi/lo conversions =================
__global__ void conv_node(const float* __restrict__ src,
                          __nv_bfloat16* __restrict__ hi,
                          __nv_bfloat16* __restrict__ lo, int useNorm) {
    long idx = (long)blockIdx.x * blockDim.x + threadIdx.x;
    if (idx >= (long)NN * KP) return;
    int n = (int)(idx / KP);
    int c = (int)(idx - (long)n * KP);
    float v = 0.0f;
    if (c < DD) {
        v = src[(long)n * DD + c];
        if (useNorm) v *= g_norm[n];
    }
    __nv_bfloat16 h = __float2bfloat16(v);
    hi[idx] = h;
    lo[idx] = __float2bfloat16(v - __bfloat162float(h));
}

// weights: B[j][k] (j = output col, k-major). transpose: B[j][k] = src[k][j].
__global__ void conv_weight(const float* __restrict__ src,
                            __nv_bfloat16* __restrict__ hi,
                            __nv_bfloat16* __restrict__ lo, int transpose) {
    int idx = blockIdx.x * blockDim.x + threadIdx.x;
    if (idx >= KP * KP) return;
    int j = idx / KP;
    int c = idx - j * KP;
    float v = 0.0f;
    if (j < DD && c < DD) v = transpose ? src[c * DD + j] : src[j * DD + c];
    __nv_bfloat16 h = __float2bfloat16(v);
    hi[idx] = h;
    lo[idx] = __float2bfloat16(v - __bfloat162float(h));
}

__global__ void tr_lw2(const float* __restrict__ lw2) {
    int idx = blockIdx.x * blockDim.x + threadIdx.x;
    if (idx >= DD * DD) return;
    int t = idx / DD, u = idx - t * DD;
    g_lw2t[u * DD + t] = lw2[idx];
}

// M[j][t] = sum_u Wih[j][u]*lw2[t][u] -> mthi/mtlo
__global__ void bmt_kernel(const float* __restrict__ Wih) {
    __shared__ float row[DD];
    int j = blockIdx.x;   // 0..207
    if (j < DD)
        for (int i = threadIdx.x; i < DD; i += 256) row[i] = Wih[j * DD + i];
    __syncthreads();
    int t = threadIdx.x;
    if (t >= KP) return;
    float s = 0.0f;
    if (j < DD && t < DD) {
#pragma unroll 4
        for (int u = 0; u < DD; u++) s += row[u] * g_lw2t[u * DD + t];
    }
    __nv_bfloat16 h = __float2bfloat16(s);
    g_mthi[j * KP + t] = h;
    g_mtlo[j * KP + t] = __float2bfloat16(s - __bfloat162float(h));
}

__global__ void bias_kernel(const float* __restrict__ b2, const float* __restrict__ Wih,
                            const float* __restrict__ bih, const float* __restrict__ bhh) {
    __shared__ float b2s[DD];
    for (int i = threadIdx.x; i < DD; i += 256) b2s[i] = b2[i];
    __syncthreads();
    int j = threadIdx.x;
    if (j >= DD) return;
    float s = bih[j] + bhh[j];
#pragma unroll 4
    for (int t = 0; t < DD; t++) s += b2s[t] * Wih[j * DD + t];
    g_bfin[j] = s;
}

// ================= mma helpers =================
__device__ __forceinline__ uint32_t smem_u32(const void* p) {
    return (uint32_t)__cvta_generic_to_shared(p);
}
__device__ __forceinline__ void ldsm4(uint32_t* r, uint32_t addr) {
    asm volatile("ldmatrix.sync.aligned.m8n8.x4.shared.b16 {%0,%1,%2,%3}, [%4];"
                 : "=r"(r[0]), "=r"(r[1]), "=r"(r[2]), "=r"(r[3]) : "r"(addr));
}
__device__ __forceinline__ void ldsm2(uint32_t* r, uint32_t addr) {
    asm volatile("ldmatrix.sync.aligned.m8n8.x2.shared.b16 {%0,%1}, [%2];"
                 : "=r"(r[0]), "=r"(r[1]) : "r"(addr));
}
__device__ __forceinline__ void mma_bf16(float* c, const uint32_t* a, const uint32_t* b) {
    asm volatile(
        "mma.sync.aligned.m16n8k16.row.col.f32.bf16.bf16.f32 "
        "{%0,%1,%2,%3}, {%4,%5,%6,%7}, {%8,%9}, {%0,%1,%2,%3};"
        : "+f"(c[0]), "+f"(c[1]), "+f"(c[2]), "+f"(c[3])
        : "r"(a[0]), "r"(a[1]), "r"(a[2]), "r"(a[3]), "r"(b[0]), "r"(b[1]));
}
__device__ __forceinline__ void cpa16(uint32_t dsts, const void* src, bool valid) {
    int sz = valid ? 16 : 0;
    asm volatile("cp.async.cg.shared.global [%0], [%1], 16, %2;"
                 :: "r"(dsts), "l"(src), "r"(sz));
}
#define CP_COMMIT() asm volatile("cp.async.commit_group;" ::: "memory")
#define CP_WAIT1()  asm volatile("cp.async.wait_group 1;" ::: "memory")
#define CP_WAIT0()  asm volatile("cp.async.wait_group 0;" ::: "memory")

// ================= pipelined 3-term MMA GEMM =================
// C[128 x 200] per CTA: C = sum_p (AhiBhi + AhiBlo + AloBhi)_p
// 8 warps 4(M)x2(N); warp 32x104. K chunks per pass: {64,64,64,16}.
template <int NPASS, bool HAS_AGG, bool WRITE_H1>
__global__ void __launch_bounds__(256, 1) mma_gemm(
    const __nv_bfloat16* __restrict__ A0h, const __nv_bfloat16* __restrict__ A0l,
    const __nv_bfloat16* __restrict__ B0h, const __nv_bfloat16* __restrict__ B0l,
    const __nv_bfloat16* __restrict__ A1h, const __nv_bfloat16* __restrict__ A1l,
    const __nv_bfloat16* __restrict__ B1h, const __nv_bfloat16* __restrict__ B1l,
    const __nv_bfloat16* __restrict__ A2h, const __nv_bfloat16* __restrict__ A2l,
    const __nv_bfloat16* __restrict__ B2h, const __nv_bfloat16* __restrict__ B2l,
    const float* __restrict__ bias, float* __restrict__ outf,
    __nv_bfloat16* __restrict__ h1hi, __nv_bfloat16* __restrict__ h1lo) {
    extern __shared__ __align__(128) char smem[];
    uint32_t sb = smem_u32(smem);

    int tid = threadIdx.x;
    int lane = tid & 31;
    int wid = tid >> 5;
    int wm = wid & 3;
    int wn = wid >> 2;
    int row0 = blockIdx.x * BM;

    float acc[2][13][4];
#pragma unroll
    for (int mi = 0; mi < 2; mi++)
#pragma unroll
        for (int nt = 0; nt < 13; nt++)
#pragma unroll
            for (int q = 0; q < 4; q++) acc[mi][nt][q] = 0.0f;

    const __nv_bfloat16* Ahp[3] = {A0h, A1h, A2h};
    const __nv_bfloat16* Alp[3] = {A0l, A1l, A2l};
    const __nv_bfloat16* Bhp[3] = {B0h, B1h, B2h};
    const __nv_bfloat16* Blp[3] = {B0l, B1l, B2l};

    const int total = NPASS * 4;

    // ---- chunk loader (cp.async) ----
    auto load_chunk = [&](int t, int stage) {
        int p = t >> 2, c = t & 3;
        int kb = c * 64;
        int sh = (c == 3) ? 1 : 3;          // uint4 per row = 1<<sh
        int msk = (1 << sh) - 1;
        uint32_t base = sb + stage * STAGE_BYTES;
        const __nv_bfloat16* Ah = Ahp[p];
        const __nv_bfloat16* Al = Alp[p];
        const __nv_bfloat16* Bh = Bhp[p];
        const __nv_bfloat16* Bl = Blp[p];
        int nA = 128 << sh;
        for (int i = tid; i < nA; i += 256) {
            int r = i >> sh, u = i & msk;
            int gr = row0 + r;
            bool v = gr < NN;
            long off = (long)gr * KP + kb + u * 8;
            cpa16(base + SO_AHI + r * 144 + u * 16, Ah + off, v);
            cpa16(base + SO_ALO + r * 144 + u * 16, Al + off, v);
        }
        int nB = 208 << sh;
        for (int i = tid; i < nB; i += 256) {
            int r = i >> sh, u = i & msk;
            long off = (long)r * KP + kb + u * 8;
            cpa16(base + SO_BHI + r * 144 + u * 16, Bh + off, true);
            cpa16(base + SO_BLO + r * 144 + u * 16, Bl + off, true);
        }
        CP_COMMIT();
    };

    // per-lane fragment address offsets (bytes, within a stage)
    uint32_t a_off = (uint32_t)((wm * 32 + (lane & 15)) * 144 + (((lane >> 4) << 3) << 1));
    uint32_t b_off = (uint32_t)((wn * 104 + (lane & 7) + ((lane >> 4) << 3)) * 144 +
                                ((((lane >> 3) & 1) << 3) << 1));
    uint32_t b2_off = (uint32_t)((wn * 104 + 96 + (lane & 7)) * 144 +
                                 ((((lane >> 3) & 1) << 3) << 1));

    load_chunk(0, 0);

#pragma unroll 1
    for (int t = 0; t < total; t++) {
        if (t + 1 < total) {
            load_chunk(t + 1, (t + 1) & 1);
            CP_WAIT1();
        } else {
            CP_WAIT0();
        }
        __syncthreads();

        int c = t & 3;
        int nk16 = (c == 3) ? 1 : 4;
        uint32_t base = sb + (t & 1) * STAGE_BYTES;
#pragma unroll
        for (int k16 = 0; k16 < 4; k16++) {
            if (k16 >= nk16) break;
            uint32_t kofs = (uint32_t)(k16 << 5);   // 16 bf16 = 32 bytes
            uint32_t ah[2][4], al[2][4];
#pragma unroll
            for (int mi = 0; mi < 2; mi++) {
                ldsm4(ah[mi], base + SO_AHI + a_off + mi * (16 * 144) + kofs);
                ldsm4(al[mi], base + SO_ALO + a_off + mi * (16 * 144) + kofs);
            }
#pragma unroll
            for (int bt = 0; bt < 6; bt++) {
                uint32_t bh[4], bl[4];
                ldsm4(bh, base + SO_BHI + b_off + bt * (16 * 144) + kofs);
                ldsm4(bl, base + SO_BLO + b_off + bt * (16 * 144) + kofs);
#pragma unroll
                for (int mi = 0; mi < 2; mi++) {
                    mma_bf16(acc[mi][2 * bt],     ah[mi], bh);
                    mma_bf16(acc[mi][2 * bt + 1], ah[mi], bh + 2);
                    mma_bf16(acc[mi][2 * bt],     ah[mi], bl);
                    mma_bf16(acc[mi][2 * bt + 1], ah[mi], bl + 2);
                    mma_bf16(acc[mi][2 * bt],     al[mi], bh);
                    mma_bf16(acc[mi][2 * bt + 1], al[mi], bh + 2);
                }
            }
            {
                uint32_t bh[2], bl[2];
                ldsm2(bh, base + SO_BHI + b2_off + kofs);
                ldsm2(bl, base + SO_BLO + b2_off + kofs);
#pragma unroll
                for (int mi = 0; mi < 2; mi++) {
                    mma_bf16(acc[mi][12], ah[mi], bh);
                    mma_bf16(acc[mi][12], ah[mi], bl);
                    mma_bf16(acc[mi][12], al[mi], bh);
                }
            }
        }
        __syncthreads();
    }

    // ---- epilogue ----
#pragma unroll
    for (int mi = 0; mi < 2; mi++) {
        int r0 = row0 + wm * 32 + mi * 16 + (lane >> 2);
#pragma unroll
        for (int half = 0; half < 2; half++) {
            int gr = r0 + half * 8;
            if (gr >= NN) continue;
            float nv = HAS_AGG ? g_norm[gr] : 0.0f;
#pragma unroll
            for (int nt = 0; nt < 13; nt++) {
                int col = wn * 104 + nt * 8 + ((lane & 3) << 1);
                if (col >= DD) continue;
                float v0 = acc[mi][nt][half * 2 + 0];
                float v1 = acc[mi][nt][half * 2 + 1];
                if (HAS_AGG) {
                    float2 ag = *(const float2*)(g_agg + (long)gr * DD + col);
                    v0 += ag.x * nv;
                    v1 += ag.y * nv;
                }
                float2 bb = *(const float2*)(bias + col);
                v0 = tanhf(v0 + bb.x);
                v1 = tanhf(v1 + bb.y);
                *(float2*)(outf + (long)gr * DD + col) = make_float2(v0, v1);
                if (WRITE_H1) {
                    __nv_bfloat16 h0b = __float2bfloat16(v0);
                    __nv_bfloat16 h1b = __float2bfloat16(v1);
                    __nv_bfloat162 hp; hp.x = h0b; hp.y = h1b;
                    __nv_bfloat162 lp;
                    lp.x = __float2bfloat16(v0 - __bfloat162float(h0b));
                    lp.y = __float2bfloat16(v1 - __bfloat162float(h1b));
                    *(__nv_bfloat162*)(h1hi + (long)gr * KP + col) = hp;
                    *(__nv_bfloat162*)(h1lo + (long)gr * KP + col) = lp;
                }
            }
        }
    }
}

// ================= launch =================
extern "C" void kernel_launch(void* const* d_in, const int* in_sizes, int n_in,
                              void* d_out, int out_size) {
    const float* node_feat = (const float*)d_in[0];
    const float* dyn       = (const float*)d_in[1];
    const int*   src       = (const int*)d_in[2];
    const int*   dst       = (const int*)d_in[3];
    const int*   et        = (const int*)d_in[4];
    const float* w1        = (const float*)d_in[5];
    const float* lw1       = (const float*)d_in[6];
    const float* b1        = (const float*)d_in[7];
    const float* w2        = (const float*)d_in[8];
    const float* lw2       = (const float*)d_in[9];
    const float* b2        = (const float*)d_in[10];
    const float* Wih       = (const float*)d_in[11];
    const float* Whh       = (const float*)d_in[12];
    const float* bih       = (const float*)d_in[13];
    const float* bhh       = (const float*)d_in[14];
    float* out = (float*)d_out;

    void *agg_p, *norm_p, *h1_p, *bfin_p;
    void *xhi, *xlo, *h1hi, *h1lo, *a2hi, *a2lo, *h0hi, *h0lo;
    void *w1hi, *w1lo, *wihhi, *wihlo, *whhhi, *whhlo, *mthi, *mtlo;
    cudaGetSymbolAddress(&agg_p, g_agg);
    cudaGetSymbolAddress(&norm_p, g_norm);
    cudaGetSymbolAddress(&h1_p, g_h1);
    cudaGetSymbolAddress(&bfin_p, g_bfin);
    cudaGetSymbolAddress(&xhi, g_xhi);     cudaGetSymbolAddress(&xlo, g_xlo);
    cudaGetSymbolAddress(&h1hi, g_h1hi);   cudaGetSymbolAddress(&h1lo, g_h1lo);
    cudaGetSymbolAddress(&a2hi, g_a2hi);   cudaGetSymbolAddress(&a2lo, g_a2lo);
    cudaGetSymbolAddress(&h0hi, g_h0hi);   cudaGetSymbolAddress(&h0lo, g_h0lo);
    cudaGetSymbolAddress(&w1hi, g_w1hi);   cudaGetSymbolAddress(&w1lo, g_w1lo);
    cudaGetSymbolAddress(&wihhi, g_wihhi); cudaGetSymbolAddress(&wihlo, g_wihlo);
    cudaGetSymbolAddress(&whhhi, g_whhhi); cudaGetSymbolAddress(&whhlo, g_whhlo);
    cudaGetSymbolAddress(&mthi, g_mthi);   cudaGetSymbolAddress(&mtlo, g_mtlo);

    cudaFuncSetAttribute(mma_gemm<1, true, true>,
                         cudaFuncAttributeMaxDynamicSharedMemorySize, SM_TOT);
    cudaFuncSetAttribute(mma_gemm<3, false, false>,
                         cudaFuncAttributeMaxDynamicSharedMemorySize, SM_TOT);

    cudaMemsetAsync(agg_p, 0, sizeof(float) * NN * DD);
    cudaMemsetAsync(norm_p, 0, sizeof(float) * NN);
    // h1hi/h1lo pad columns (200..207) must be zero; epilogue writes only <200
    cudaMemsetAsync(h1hi, 0, sizeof(__nv_bfloat16) * (size_t)NN * KP);
    cudaMemsetAsync(h1lo, 0, sizeof(__nv_bfloat16) * (size_t)NN * KP);

    deg_kernel<<<(EE + 255) / 256, 256>>>(dst);
    norm_kernel<<<(NN + 255) / 256, 256>>>();

    conv_weight<<<(KP * KP + 255) / 256, 256>>>(lw1, (__nv_bfloat16*)w1hi, (__nv_bfloat16*)w1lo, 1);
    conv_weight<<<(KP * KP + 255) / 256, 256>>>(Wih, (__nv_bfloat16*)wihhi, (__nv_bfloat16*)wihlo, 0);
    conv_weight<<<(KP * KP + 255) / 256, 256>>>(Whh, (__nv_bfloat16*)whhhi, (__nv_bfloat16*)whhlo, 0);
    tr_lw2<<<(DD * DD + 255) / 256, 256>>>(lw2);
    bmt_kernel<<<KP, 256>>>(Wih);
    bias_kernel<<<1, 256>>>(b2, Wih, bih, bhh);

    const long nconv = (long)NN * KP;
    conv_node<<<(int)((nconv + 255) / 256), 256>>>(node_feat, (__nv_bfloat16*)xhi, (__nv_bfloat16*)xlo, 0);
    conv_node<<<(int)((nconv + 255) / 256), 256>>>(dyn, (__nv_bfloat16*)h0hi, (__nv_bfloat16*)h0lo, 0);

    // layer 1
    edge_kernel<<<(EE * 50 + 255) / 256, 256>>>(node_feat, src, dst, et, w1);
    mma_gemm<1, true, true><<<NTILES, 256, SM_TOT>>>(
        (const __nv_bfloat16*)xhi, (const __nv_bfloat16*)xlo,
        (const __nv_bfloat16*)w1hi, (const __nv_bfloat16*)w1lo,
        nullptr, nullptr, nullptr, nullptr,
        nullptr, nullptr, nullptr, nullptr,
        b1, (float*)h1_p, (__nv_bfloat16*)h1hi, (__nv_bfloat16*)h1lo);

    // layer 2 scatter + convert
    cudaMemsetAsync(agg_p, 0, sizeof(float) * NN * DD);
    edge_kernel<<<(EE * 50 + 255) / 256, 256>>>((const float*)h1_p, src, dst, et, w2);
    conv_node<<<(int)((nconv + 255) / 256), 256>>>((const float*)agg_p,
        (__nv_bfloat16*)a2hi, (__nv_bfloat16*)a2lo, 1);

    // fused final: out = tanh( agg2n@Wih^T + h1@(lw2@Wih^T) + h0@Whh^T + bfin )
    mma_gemm<3, false, false><<<NTILES, 256, SM_TOT>>>(
        (const __nv_bfloat16*)a2hi, (const __nv_bfloat16*)a2lo,
        (const __nv_bfloat16*)wihhi, (const __nv_bfloat16*)wihlo,
        (const __nv_bfloat16*)h1hi, (const __nv_bfloat16*)h1lo,
        (const __nv_bfloat16*)mthi, (const __nv_bfloat16*)mtlo,
        (const __nv_bfloat16*)h0hi, (const __nv_bfloat16*)h0lo,
        (const __nv_bfloat16*)whhhi, (const __nv_bfloat16*)whhlo,
        (const float*)bfin_p, out, nullptr, nullptr);
}